// round 10
// baseline (speedup 1.0000x reference)
#include <cuda_runtime.h>
#include <cstdint>

#define NT    512
#define NCTA  592           // 4 * 148 persistent CTAs
#define ROWB  22200         // bytes per row (5550 floats)

static __device__ float g_partial[NCTA];
static __device__ int   g_count = 0;

__device__ __forceinline__ void cpa16(unsigned dst, const void* src) {
    asm volatile("cp.async.cg.shared.global [%0], [%1], 16;" :: "r"(dst), "l"(src));
}
__device__ __forceinline__ void cpa_commit() {
    asm volatile("cp.async.commit_group;");
}
template <int N>
__device__ __forceinline__ void cpa_wait() {
    asm volatile("cp.async.wait_group %0;" :: "n"(N) : "memory");
}

__global__ void __launch_bounds__(NT, 4) hjsd(const float* __restrict__ y,
                                              const int* __restrict__ tgt,
                                              float* __restrict__ out, int batch) {
    __shared__ float4 buf[2][1389];        // two row frames (16B grid)
    __shared__ float  scr[2][6 * 16];      // parity-doubled partials
    __shared__ int    sIsLast;

    const int t    = threadIdx.x;
    const int lane = t & 31;
    const int w    = t >> 5;
    const int bx   = blockIdx.x;
    const int stride = gridDim.x;

    // Row byte base = 22200*r; 22200 % 16 == 8 and stride is even, so all of
    // this CTA's rows share parity. Frame = row shifted down by 8B when odd,
    // so the 16B grid aligns; row data starts at float offset d in the frame.
    const int odd = bx & 1;
    const int d   = odd ? 2 : 0;

    const unsigned sb[2] = { (unsigned)__cvta_generic_to_shared(&buf[0][0]),
                             (unsigned)__cvta_generic_to_shared(&buf[1][0]) };

    // Per-warp float4 ranges (warps 1..15).
    // level-1 slice: floats [d+50+32(w-1), d+50+32w)
    // level-2 slice: floats [d+550+320(w-1), d+550+320w)   (groups 32(w-1)..32w-1)
    int f1s = 0, f1e = 0, f2s = 0, f2e = 0;
    if (w > 0) {
        int a1 = d + 50 + 32 * (w - 1), b1 = a1 + 32;
        int a2 = d + 550 + 320 * (w - 1), b2 = a2 + 320;
        f1s = a1 >> 2; f1e = ((b1 - 1) >> 2) + 1;
        f2s = a2 >> 2; f2e = ((b2 - 1) >> 2) + 1;
    }

    // Prefetch this warp's slices of row r into buffer bi.
    auto prefetch = [&](int bi, int r) {
        const float4* src = (const float4*)((const char*)y + (size_t)r * ROWB - (size_t)(d ? 8 : 0));
        unsigned dst = sb[bi];
#pragma unroll 1
        for (int f = f2s + lane; f < f2e; f += 32) cpa16(dst + (unsigned)f * 16u, src + f);
        if (f1s + lane < f1e) cpa16(dst + (unsigned)(f1s + lane) * 16u, src + f1s + lane);
    };

    int r = bx;
    int cur = 0, par = 0;
    if (w > 0 && r < batch) prefetch(0, r);
    cpa_commit();

    float rowsum = 0.f;

    for (; r < batch; r += stride, par ^= 1) {
        const int nr = r + stride;
        const int gt = tgt[r];                         // broadcast

        // 6 block-wide partials: S1, S2, Sc1, A1, B1, CEraw
        float p0 = 0.f, p1 = 0.f, p2 = 0.f, p3 = 0.f, p4 = 0.f, p5 = 0.f;
        // warp-0-local level-0 sums
        float S0w = 0.f, Sc0w = 0.f, A0w = 0.f, B0w = 0.f;

        if (w > 0) {
            if (nr < batch) { prefetch(cur ^ 1, nr); cpa_commit(); cpa_wait<1>(); }
            else            { cpa_wait<0>(); }
            __syncwarp();                              // own-warp data visible

            const float* sx = (const float*)&buf[cur][0];
            const int g = t - 32;                      // group 0..479
            const float2* g2 = (const float2*)(sx + d + 550 + 10 * g);
            float c = 0.f, s2 = 0.f;
#pragma unroll
            for (int i = 0; i < 5; i++) {
                float2 v = g2[i];
                c  += v.x + v.y;
                s2 += __expf(v.x) + __expf(v.y);
            }
            float x1  = sx[d + 50 + g];
            float e1  = __expf(x1);
            float ec1 = __expf(c);
            float dm  = c - x1;
            p0 = e1; p1 = s2; p2 = ec1; p3 = ec1 * dm; p4 = e1 * dm;
            if (g == gt / 10)                          // CE: owner holds both
                p5 = x1 + sx[d + 550 + gt];
        } else {
            // ---- warp 0: level-0 + level-1 child sums + last 20 groups, all LDG ----
            const float* row = y + (size_t)r * 5550;
#pragma unroll
            for (int s = 0; s < 2; s++) {
                int j = lane + 32 * s;
                if (j < 50) {
                    float x0 = __ldg(row + j);
                    const float2* h2 = (const float2*)(row + 50 + 10 * j);
                    float c0 = 0.f;
#pragma unroll
                    for (int i = 0; i < 5; i++) { float2 v = __ldg(h2 + i); c0 += v.x + v.y; }
                    float e0  = __expf(x0);
                    float ec0 = __expf(c0);
                    float dm  = c0 - x0;
                    S0w += e0; Sc0w += ec0; A0w += ec0 * dm; B0w += e0 * dm;
                    if (j == gt / 100) p5 += x0;       // CE level-0 raw
                }
            }
            if (lane < 20) {                           // groups 480..499
                const int g = 480 + lane;
                const float2* g2 = (const float2*)(row + 550 + 10 * g);
                float c = 0.f, s2 = 0.f;
#pragma unroll
                for (int i = 0; i < 5; i++) {
                    float2 v = __ldg(g2 + i);
                    c  += v.x + v.y;
                    s2 += __expf(v.x) + __expf(v.y);
                }
                float x1  = __ldg(row + 50 + g);
                float e1  = __expf(x1);
                float ec1 = __expf(c);
                float dm  = c - x1;
                p0 = e1; p1 = s2; p2 = ec1; p3 = ec1 * dm; p4 = e1 * dm;
                if (g == gt / 10)
                    p5 = x1 + __ldg(row + 550 + gt);
            }
            // warp-local tree for level-0 sums
#pragma unroll
            for (int o = 16; o; o >>= 1) {
                S0w  += __shfl_xor_sync(0xffffffffu, S0w,  o);
                Sc0w += __shfl_xor_sync(0xffffffffu, Sc0w, o);
                A0w  += __shfl_xor_sync(0xffffffffu, A0w,  o);
                B0w  += __shfl_xor_sync(0xffffffffu, B0w,  o);
            }
        }

        // ---- per-warp tree over the 6 shared partials, one STS set per warp ----
#pragma unroll
        for (int o = 16; o; o >>= 1) {
            p0 += __shfl_xor_sync(0xffffffffu, p0, o);
            p1 += __shfl_xor_sync(0xffffffffu, p1, o);
            p2 += __shfl_xor_sync(0xffffffffu, p2, o);
            p3 += __shfl_xor_sync(0xffffffffu, p3, o);
            p4 += __shfl_xor_sync(0xffffffffu, p4, o);
            p5 += __shfl_xor_sync(0xffffffffu, p5, o);
        }
        if (lane == 0) {
            float* s = scr[par];
            s[0 * 16 + w] = p0; s[1 * 16 + w] = p1; s[2 * 16 + w] = p2;
            s[3 * 16 + w] = p3; s[4 * 16 + w] = p4; s[5 * 16 + w] = p5;
        }
        __syncthreads();                               // the ONLY block barrier

        // ---- stage 2 + epilogue: warp 0 only (overlaps others' next row) ----
        if (w == 0) {
            const float* s = scr[par];
            float v[6];
#pragma unroll
            for (int k = 0; k < 6; k++) {
                float x = (lane < 16) ? s[k * 16 + lane] : 0.f;
#pragma unroll
                for (int o = 8; o; o >>= 1) x += __shfl_xor_sync(0xffffffffu, x, o);
                v[k] = x;
            }
            if (lane == 0) {
                float S1 = v[0], S2 = v[1], Sc1 = v[2], A1 = v[3], B1 = v[4], CEr = v[5];
                float L0 = __logf(S0w), L1 = __logf(S1), L2 = __logf(S2);
                rowsum += (0.25f / 500.f) * (__fdividef(A1, Sc1) - __fdividef(B1, S1))
                        + (0.25f / 50.f)  * (__fdividef(A0w, Sc0w) - __fdividef(B0w, S0w))
                        - 0.5f * (CEr - L0 - L1 - L2);
            }
        }
        cur ^= 1;
    }

    // ---- one partial per CTA, deterministic last-CTA reduction ----
    if (t == 0) {
        g_partial[bx] = rowsum;
        __threadfence();
        int prev = atomicAdd(&g_count, 1);
        sIsLast = (prev == (int)gridDim.x - 1) ? 1 : 0;
    }
    __syncthreads();

    if (sIsLast) {
        float s = 0.f;
        for (int i = t; i < (int)gridDim.x; i += NT) s += __ldcg(&g_partial[i]);
#pragma unroll
        for (int o = 16; o; o >>= 1) s += __shfl_xor_sync(0xffffffffu, s, o);
        if (lane == 0) scr[0][w] = s;
        __syncthreads();
        if (w == 0) {
            float v = (lane < 16) ? scr[0][lane] : 0.f;
#pragma unroll
            for (int o = 8; o; o >>= 1) v += __shfl_xor_sync(0xffffffffu, v, o);
            if (lane == 0) {
                out[0] = v / (float)batch;
                g_count = 0;   // reset for next graph replay
            }
        }
    }
}

extern "C" void kernel_launch(void* const* d_in, const int* in_sizes, int n_in,
                              void* d_out, int out_size) {
    const float* y   = (const float*)d_in[0];   // y_pred [B, 5550] fp32
    const int*   tgt = (const int*)d_in[1];     // target [B] int32
    (void)d_in[2];                              // parent: fixed structure, derived arithmetically
    int batch = in_sizes[1];

    hjsd<<<NCTA, NT>>>(y, tgt, (float*)d_out, batch);
}

// round 12
// speedup vs baseline: 1.8784x; 1.8784x over previous
#include <cuda_runtime.h>
#include <cstdint>

#define NT    256
#define NWP   8             // warps per CTA
#define NCTA  592           // 4 * 148
#define TOTW  (NCTA * NWP)  // 4736 warps, >= 4096 rows

static __device__ float g_partial[NCTA];
static __device__ int   g_count = 0;

__device__ __forceinline__ void cpa8(unsigned dst, const void* src) {
    asm volatile("cp.async.ca.shared.global [%0], [%1], 8;" :: "r"(dst), "l"(src));
}
__device__ __forceinline__ void cpa_commit() {
    asm volatile("cp.async.commit_group;");
}
template <int N>
__device__ __forceinline__ void cpa_wait() {
    asm volatile("cp.async.wait_group %0;" :: "n"(N) : "memory");
}

__global__ void __launch_bounds__(NT, 4) hjsd(const float* __restrict__ y,
                                              const int* __restrict__ tgt,
                                              float* __restrict__ out, int batch) {
    __shared__ float x01[NWP][552];      // level-0/1 region (550 floats)
    __shared__ float tb[NWP][2][320];    // level-2 tile double buffer
    __shared__ float swarp[NWP];
    __shared__ int   sIsLast;

    const int t    = threadIdx.x;
    const int lane = t & 31;
    const int w    = t >> 5;
    const int bx   = blockIdx.x;

    const unsigned xb   = (unsigned)__cvta_generic_to_shared(&x01[w][0]);
    const unsigned tbb0 = (unsigned)__cvta_generic_to_shared(&tb[w][0][0]);
    const unsigned tbb1 = (unsigned)__cvta_generic_to_shared(&tb[w][1][0]);

    float rowsum = 0.f;

    // Interleaved row assignment: idle warps (high w) spread across all CTAs.
    for (int r = bx + NCTA * w; r < batch; r += TOTW) {
        const float*  row  = y + (size_t)r * 5550;
        const float2* row2 = (const float2*)row;      // 22200*r % 8 == 0

        // CE raw gathers: lane-0 LDGs issued early, consumed at row end.
        int gt = 0; float xg0 = 0.f, xg1 = 0.f, xg2 = 0.f;
        if (lane == 0) {
            gt  = __ldg(tgt + r);
            xg2 = __ldg(row + 550 + gt);
            xg1 = __ldg(row + 50 + gt / 10);
            xg0 = __ldg(row + gt / 100);
        }

        // G0: x01 region (275 f2) + tile 0 (160 f2)
#pragma unroll
        for (int k = 0; k < 9; k++) {
            int i = lane + 32 * k;
            if (i < 275) cpa8(xb + (unsigned)i * 8u, row2 + i);
        }
#pragma unroll
        for (int k = 0; k < 5; k++) {
            int i = lane + 32 * k;
            cpa8(tbb0 + (unsigned)i * 8u, row2 + 275 + i);
        }
        cpa_commit();

        float S1 = 0.f, S2 = 0.f, Sc1 = 0.f, A1 = 0.f, B1 = 0.f;

#pragma unroll 1
        for (int T = 0; T < 16; T++) {
            if (T < 15) {                      // prefetch tile T+1
                const int nf2 = (T < 14) ? 160 : 100;   // tile 15 = 20 groups
                const float2* src = row2 + 275 + 160 * (T + 1);
                const unsigned dst = ((T + 1) & 1) ? tbb1 : tbb0;
#pragma unroll
                for (int k = 0; k < 5; k++) {
                    int i = lane + 32 * k;
                    if (i < nf2) cpa8(dst + (unsigned)i * 8u, src + i);
                }
                cpa_commit();
                cpa_wait<1>();                 // tile T (and x01) complete
            } else {
                cpa_commit();                  // empty group keeps counts aligned
                cpa_wait<0>();
            }
            __syncwarp();

            const int ng = (T < 15) ? 32 : 20;
            if (lane < ng) {
                const float2* gp = (const float2*)&tb[w][T & 1][0] + 5 * lane;
                float c = 0.f, s2 = 0.f;
#pragma unroll
                for (int i = 0; i < 5; i++) {
                    float2 v = gp[i];
                    c  += v.x + v.y;
                    s2 += __expf(v.x) + __expf(v.y);
                }
                float x1v = x01[w][50 + 32 * T + lane];
                float e1  = __expf(x1v);
                float ec1 = __expf(c);
                float dm  = c - x1v;
                S1 += e1; S2 += s2; Sc1 += ec1; A1 += ec1 * dm; B1 += e1 * dm;
            }
            __syncwarp();                      // tile buffer free before next refill
        }

        // ---- level 0 (50 nodes) from the staged x01 region ----
        float S0 = 0.f, Sc0 = 0.f, A0 = 0.f, B0 = 0.f;
#pragma unroll
        for (int s = 0; s < 2; s++) {
            int j = lane + 32 * s;
            if (j < 50) {
                float x0 = x01[w][j];
                const float2* h2 = (const float2*)&x01[w][50 + 10 * j];
                float c0 = 0.f;
#pragma unroll
                for (int i = 0; i < 5; i++) { float2 v = h2[i]; c0 += v.x + v.y; }
                float e0  = __expf(x0);
                float ec0 = __expf(c0);
                float dm  = c0 - x0;
                S0 += e0; Sc0 += ec0; A0 += ec0 * dm; B0 += e0 * dm;
            }
        }

        // ---- single warp-level 9-value reduction ----
#pragma unroll
        for (int o = 16; o; o >>= 1) {
            S1  += __shfl_xor_sync(0xffffffffu, S1,  o);
            S2  += __shfl_xor_sync(0xffffffffu, S2,  o);
            Sc1 += __shfl_xor_sync(0xffffffffu, Sc1, o);
            A1  += __shfl_xor_sync(0xffffffffu, A1,  o);
            B1  += __shfl_xor_sync(0xffffffffu, B1,  o);
            S0  += __shfl_xor_sync(0xffffffffu, S0,  o);
            Sc0 += __shfl_xor_sync(0xffffffffu, Sc0, o);
            A0  += __shfl_xor_sync(0xffffffffu, A0,  o);
            B0  += __shfl_xor_sync(0xffffffffu, B0,  o);
        }

        if (lane == 0) {
            // sym-KL per level = A/Sc - B/Sp (log-sum terms cancel: both pdfs sum to 1)
            float L0 = __logf(S0), L1 = __logf(S1), L2 = __logf(S2);
            rowsum += (0.25f / 500.f) * (__fdividef(A1, Sc1) - __fdividef(B1, S1))
                    + (0.25f / 50.f)  * (__fdividef(A0, Sc0) - __fdividef(B0, S0))
                    - 0.5f * ((xg0 - L0) + (xg1 - L1) + (xg2 - L2));
        }
    }

    // ---- CTA reduction (8 warp partials), then last-CTA final ----
    if (lane == 0) swarp[w] = rowsum;
    __syncthreads();
    if (w == 0) {
        float v = (lane < NWP) ? swarp[lane] : 0.f;
#pragma unroll
        for (int o = 4; o; o >>= 1) v += __shfl_xor_sync(0xffffffffu, v, o);
        if (lane == 0) {
            g_partial[bx] = v;
            __threadfence();
            int prev = atomicAdd(&g_count, 1);
            sIsLast = (prev == (int)gridDim.x - 1) ? 1 : 0;
        }
    }
    __syncthreads();

    if (sIsLast) {
        float s = 0.f;
        for (int i = t; i < (int)gridDim.x; i += NT) s += __ldcg(&g_partial[i]);
#pragma unroll
        for (int o = 16; o; o >>= 1) s += __shfl_xor_sync(0xffffffffu, s, o);
        if (lane == 0) swarp[w] = s;
        __syncthreads();
        if (w == 0) {
            float v = (lane < NWP) ? swarp[lane] : 0.f;
#pragma unroll
            for (int o = 4; o; o >>= 1) v += __shfl_xor_sync(0xffffffffu, v, o);
            if (lane == 0) {
                out[0] = v / (float)batch;
                g_count = 0;   // reset for next graph replay
            }
        }
    }
}

extern "C" void kernel_launch(void* const* d_in, const int* in_sizes, int n_in,
                              void* d_out, int out_size) {
    const float* y   = (const float*)d_in[0];   // y_pred [B, 5550] fp32
    const int*   tgt = (const int*)d_in[1];     // target [B] int32
    (void)d_in[2];                              // parent: fixed structure, derived arithmetically
    int batch = in_sizes[1];

    hjsd<<<NCTA, NT>>>(y, tgt, (float*)d_out, batch);
}